// round 16
// baseline (speedup 1.0000x reference)
#include <cuda_runtime.h>
#include <cuda_fp16.h>
#include <math.h>
#include <stdint.h>

// ---------------------------------------------------------------------------
// Problem constants: B=1, S=2048, H=4096, NH=32, NKV=8, HD=128
// ---------------------------------------------------------------------------
#define S_LEN 2048
#define HDIM  4096
#define NH    32
#define NKV   8
#define HD    128
#define SCALING 0.08838834764831843f  // 128^-0.5

// Device-global scratch (no runtime allocation allowed)
__device__ __half g_hsh[S_LEN * HDIM];
__device__ __half g_wqh[HDIM * HDIM];
__device__ __half g_wkh[NKV * HD * HDIM];
__device__ __half g_wvh[NKV * HD * HDIM];
__device__ __half g_woh[HDIM * HDIM];
__device__ __half g_qh [S_LEN * NH  * HD];   // fp16 Q post-rope
__device__ __half g_kh [S_LEN * NKV * HD];   // fp16 K post-rope
__device__ __half g_vt [NKV * HD * S_LEN];   // V^T per kv-head, fp16
__device__ __half g_aoh[S_LEN * NH  * HD];   // attn_out fp16
__device__ __half g_wh [(size_t)NH * S_LEN * S_LEN];      // fp16 weights operand
__device__ float  g_w_scratch[(size_t)NH * S_LEN * S_LEN]; // fallback fp32 W

// ---------------------------------------------------------------------------
// Helpers
// ---------------------------------------------------------------------------
__device__ __forceinline__ void mma_f16(float* c, const uint32_t* a,
                                        uint32_t b0, uint32_t b1) {
    asm volatile(
        "mma.sync.aligned.m16n8k16.row.col.f32.f16.f16.f32 "
        "{%0,%1,%2,%3}, {%4,%5,%6,%7}, {%8,%9}, {%0,%1,%2,%3};\n"
        : "+f"(c[0]), "+f"(c[1]), "+f"(c[2]), "+f"(c[3])
        : "r"(a[0]), "r"(a[1]), "r"(a[2]), "r"(a[3]), "r"(b0), "r"(b1));
}
__device__ __forceinline__ void ldsm4(uint32_t* r, uint32_t addr) {
    asm volatile("ldmatrix.sync.aligned.m8n8.x4.shared.b16 {%0,%1,%2,%3}, [%4];"
        : "=r"(r[0]), "=r"(r[1]), "=r"(r[2]), "=r"(r[3]) : "r"(addr));
}
__device__ __forceinline__ void cp16(uint32_t dst, const void* src) {
    asm volatile("cp.async.cg.shared.global [%0], [%1], 16;" :: "r"(dst), "l"(src));
}
#define CP_COMMIT() asm volatile("cp.async.commit_group;")
#define CP_WAIT1()  asm volatile("cp.async.wait_group 1;")
#define CP_WAIT0()  asm volatile("cp.async.wait_group 0;")

// Tile geometry: CTA 128x128, K-chunk 64 (128B fp16 rows, Swizzle<3,3,3>).
#define BM 128
#define TILE_B 16384       // A tile: 128 rows x 128B
#define NSTAGE 3
#define DYN_SMEM_128 (NSTAGE * (TILE_B + 128 * 128))   // 98304

// ---------------------------------------------------------------------------
// General FP16 GEMM:  C[z] = alpha * A[z] @ B[z>>bShift]^T
// A[M,K] k-major fp16 (lda), B[N,K] k-major fp16 (ldb). C fp32 or fp16.
// 512 threads, 16 warps (4x4), warp tile 32x32.
// mode: 0 dense, 1 causal (skip bx>by; upper tiles zeroed elsewhere),
//       2 K clipped to (by+1)*128.
// Triangular modes run heavy rows first (by remapped descending).
// Smem: 16B chunk c of row r at byte r*128 + ((c ^ (r&7))<<4).
// ---------------------------------------------------------------------------
template<int BNT>
__global__ __launch_bounds__(512) void mm_f16(
    const __half* __restrict__ A, const __half* __restrict__ B, void* __restrict__ Cv,
    int K, int lda, int ldb, int ldc,
    long long bsA, long long bsB, int bShift, long long bsC,
    float alpha, int mode, int outF16)
{
    constexpr int BTILE = BNT * 128;
    constexpr int STGB  = TILE_B + BTILE;
    constexpr int NI    = BNT / 64;

    const int bx = blockIdx.x, bz = blockIdx.z;
    const int by = (mode != 0) ? ((int)gridDim.y - 1 - (int)blockIdx.y)
                               : (int)blockIdx.y;          // heavy-first for causal
    const int tid = threadIdx.x;

    if (mode == 1 && bx > by) return;

    A += (long long)bz * bsA;
    B += (long long)(bz >> bShift) * bsB;

    const int Ktot = (mode == 2) ? min(K, (by + 1) * BM) : K;
    const int NT = Ktot >> 6;

    extern __shared__ __align__(128) char smem[];
    const uint32_t sb0 = (uint32_t)__cvta_generic_to_shared(smem);

    const int lane = tid & 31;
    const int w    = tid >> 5;
    const int wm   = w >> 2;
    const int wn   = w & 3;
    const int t4   = lane >> 2;
    const int l4   = lane & 3;

    const int rr = tid >> 2;
    const int cc = tid & 3;
    const uint32_t offA0 = (uint32_t)(rr * 128 + (((cc    ) ^ (rr & 7)) << 4));
    const uint32_t offA1 = (uint32_t)(rr * 128 + (((cc + 4) ^ (rr & 7)) << 4));
    const __half* gA = A + (long long)(by * BM + rr) * lda + cc * 8;
    const __half* gB = B + (long long)(bx * BNT + rr) * ldb + cc * 8;

    uint32_t aoff[4], boff[4];
    {
        const int ra = wm * 32 + (lane & 15);
        const int rb = wn * (BNT / 4) + (lane & 15);
        #pragma unroll
        for (int ks = 0; ks < 4; ks++) {
            const int cha = ks * 2 + (lane >> 4);
            aoff[ks] = (uint32_t)(ra * 128 + ((cha ^ (ra & 7)) << 4));
            boff[ks] = (uint32_t)(TILE_B + rb * 128 + ((cha ^ (rb & 7)) << 4));
        }
    }

    float acc[2][2 * NI][4];
    #pragma unroll
    for (int i = 0; i < 2; i++)
        #pragma unroll
        for (int j = 0; j < 2 * NI; j++)
            #pragma unroll
            for (int r = 0; r < 4; r++) acc[i][j][r] = 0.f;

    #pragma unroll
    for (int s = 0; s < 2; s++) {
        if (s < NT) {
            const uint32_t d = sb0 + s * STGB;
            const __half* a0 = gA + s * 64;
            const __half* b0 = gB + s * 64;
            cp16(d + offA0, a0);
            cp16(d + offA1, a0 + 32);
            cp16(d + TILE_B + offA0, b0);
            cp16(d + TILE_B + offA1, b0 + 32);
        }
        CP_COMMIT();
    }

    for (int t = 0; t < NT; t++) {
        CP_WAIT1();
        __syncthreads();
        const uint32_t sb = sb0 + (t % NSTAGE) * STGB;

        #pragma unroll
        for (int ks = 0; ks < 4; ks++) {
            uint32_t a[2][4], b[NI][4];
            #pragma unroll
            for (int mi = 0; mi < 2; mi++) ldsm4(a[mi], sb + aoff[ks] + mi * 2048);
            #pragma unroll
            for (int p = 0; p < NI; p++)   ldsm4(b[p],  sb + boff[ks] + p * 2048);
            #pragma unroll
            for (int mi = 0; mi < 2; mi++)
                #pragma unroll
                for (int p = 0; p < NI; p++) {
                    mma_f16(acc[mi][p * 2 + 0], a[mi], b[p][0], b[p][2]);
                    mma_f16(acc[mi][p * 2 + 1], a[mi], b[p][1], b[p][3]);
                }
        }

        const int tn = t + 2;
        if (tn < NT) {
            const uint32_t d = sb0 + (tn % NSTAGE) * STGB;
            const __half* a0 = gA + tn * 64;
            const __half* b0 = gB + tn * 64;
            cp16(d + offA0, a0);
            cp16(d + offA1, a0 + 32);
            cp16(d + TILE_B + offA0, b0);
            cp16(d + TILE_B + offA1, b0 + 32);
        }
        CP_COMMIT();
    }

    #pragma unroll
    for (int mi = 0; mi < 2; mi++) {
        const int r0 = by * BM + wm * 32 + mi * 16 + t4;
        #pragma unroll
        for (int ni = 0; ni < 2 * NI; ni++) {
            const int c0 = bx * BNT + wn * (BNT / 4) + ni * 8 + 2 * l4;
            float v0 = acc[mi][ni][0] * alpha, v1 = acc[mi][ni][1] * alpha;
            float v2 = acc[mi][ni][2] * alpha, v3 = acc[mi][ni][3] * alpha;
            if (outF16) {
                __half* C = (__half*)Cv + (long long)bz * bsC;
                *reinterpret_cast<__half2*>(&C[(long long)r0 * ldc + c0]) =
                    __floats2half2_rn(v0, v1);
                *reinterpret_cast<__half2*>(&C[(long long)(r0 + 8) * ldc + c0]) =
                    __floats2half2_rn(v2, v3);
            } else {
                float* C = (float*)Cv + (long long)bz * bsC;
                *reinterpret_cast<float2*>(&C[(long long)r0 * ldc + c0]) = make_float2(v0, v1);
                *reinterpret_cast<float2*>(&C[(long long)(r0 + 8) * ldc + c0]) = make_float2(v2, v3);
            }
        }
    }
}

// ---------------------------------------------------------------------------
// Merged QKV projection + RoPE + V-transpose + causal-W zero-fill.
// grid (48, 96): by<16 heavy CTAs; by>=16 zero one strictly-upper W tile.
// ---------------------------------------------------------------------------
#define STG128 (TILE_B + 128 * 128)
__global__ __launch_bounds__(512) void qkv_rope(
    const __half* __restrict__ hsA,
    const __half* __restrict__ wq, const __half* __restrict__ wk,
    const __half* __restrict__ wv,
    __half* __restrict__ qh, __half* __restrict__ kh, __half* __restrict__ vt,
    const float* __restrict__ cosb, const float* __restrict__ sinb,
    float* __restrict__ Wz)
{
    const int bx = blockIdx.x, by = blockIdx.y;
    const int tid  = threadIdx.x;

    if (by >= 16) {
        const int t = (by - 16) * 48 + bx;      // 0..3839
        const int head = t / 120;
        int p = t % 120;
        int r = 0;
        while (p >= 15 - r) { p -= 15 - r; r++; }
        const int c = r + 1 + p;                // c > r
        float* Wt = Wz + (long long)head * S_LEN * S_LEN;
        const float4 z = make_float4(0.f, 0.f, 0.f, 0.f);
        #pragma unroll 4
        for (int i = tid; i < 128 * 32; i += 512) {
            const int rr3 = i >> 5, cc3 = (i & 31) << 2;
            *reinterpret_cast<float4*>(
                &Wt[(long long)(r * 128 + rr3) * S_LEN + c * 128 + cc3]) = z;
        }
        return;
    }

    const __half* Bw; int h; int epi;
    if (bx < 32)      { Bw = wq; h = bx;      epi = 0; }
    else if (bx < 40) { Bw = wk; h = bx - 32; epi = 1; }
    else              { Bw = wv; h = bx - 40; epi = 2; }

    extern __shared__ __align__(128) char smem[];
    const uint32_t sb0 = (uint32_t)__cvta_generic_to_shared(smem);
    float* smT = reinterpret_cast<float*>(smem);

    const int lane = tid & 31;
    const int w    = tid >> 5;
    const int wm   = w >> 2;
    const int wn   = w & 3;
    const int t4   = lane >> 2;
    const int l4   = lane & 3;

    const int rr = tid >> 2;
    const int cc = tid & 3;
    const uint32_t offA0 = (uint32_t)(rr * 128 + (((cc    ) ^ (rr & 7)) << 4));
    const uint32_t offA1 = (uint32_t)(rr * 128 + (((cc + 4) ^ (rr & 7)) << 4));
    const __half* gA = hsA + (long long)(by * BM + rr) * HDIM + cc * 8;
    const __half* gB = Bw  + (long long)(h  * 128 + rr) * HDIM + cc * 8;

    uint32_t aoff[4], boff[4];
    {
        const int ra = wm * 32 + (lane & 15);
        const int rb = wn * 32 + (lane & 15);
        #pragma unroll
        for (int ks = 0; ks < 4; ks++) {
            const int cha = ks * 2 + (lane >> 4);
            aoff[ks] = (uint32_t)(ra * 128 + ((cha ^ (ra & 7)) << 4));
            boff[ks] = (uint32_t)(TILE_B + rb * 128 + ((cha ^ (rb & 7)) << 4));
        }
    }

    float acc[2][4][4];
    #pragma unroll
    for (int i = 0; i < 2; i++)
        #pragma unroll
        for (int j = 0; j < 4; j++)
            #pragma unroll
            for (int r = 0; r < 4; r++) acc[i][j][r] = 0.f;

    const int NT = HDIM >> 6;

    #pragma unroll
    for (int s = 0; s < 2; s++) {
        const uint32_t d = sb0 + s * STG128;
        const __half* a0 = gA + s * 64;
        const __half* b0 = gB + s * 64;
        cp16(d + offA0,          a0);
        cp16(d + offA1,          a0 + 32);
        cp16(d + TILE_B + offA0, b0);
        cp16(d + TILE_B + offA1, b0 + 32);
        CP_COMMIT();
    }

    for (int t = 0; t < NT; t++) {
        CP_WAIT1();
        __syncthreads();
        const uint32_t sb = sb0 + (t % NSTAGE) * STG128;

        #pragma unroll
        for (int ks = 0; ks < 4; ks++) {
            uint32_t a[2][4], b[2][4];
            #pragma unroll
            for (int mi = 0; mi < 2; mi++) ldsm4(a[mi], sb + aoff[ks] + mi * 2048);
            #pragma unroll
            for (int p = 0; p < 2; p++)    ldsm4(b[p],  sb + boff[ks] + p * 2048);
            #pragma unroll
            for (int mi = 0; mi < 2; mi++)
                #pragma unroll
                for (int p = 0; p < 2; p++) {
                    mma_f16(acc[mi][p * 2 + 0], a[mi], b[p][0], b[p][2]);
                    mma_f16(acc[mi][p * 2 + 1], a[mi], b[p][1], b[p][3]);
                }
        }

        const int tn = t + 2;
        if (tn < NT) {
            const uint32_t d = sb0 + (tn % NSTAGE) * STG128;
            const __half* a0 = gA + tn * 64;
            const __half* b0 = gB + tn * 64;
            cp16(d + offA0,          a0);
            cp16(d + offA1,          a0 + 32);
            cp16(d + TILE_B + offA0, b0);
            cp16(d + TILE_B + offA1, b0 + 32);
        }
        CP_COMMIT();
    }

    CP_WAIT0();
    __syncthreads();

    if (epi < 2) {
        const int nh = (epi == 0) ? NH : NKV;
        __half* outp = (epi == 0) ? qh : kh;
        if (wn >= 2) {
            #pragma unroll
            for (int mi = 0; mi < 2; mi++)
                #pragma unroll
                for (int ni = 0; ni < 4; ni++) {
                    const int d2 = (wn - 2) * 32 + ni * 8 + 2 * l4;
                    #pragma unroll
                    for (int p = 0; p < 2; p++) {
                        const int r = wm * 32 + mi * 16 + t4 + p * 8;
                        smT[d2 * 132 + r]       = acc[mi][ni][p * 2 + 0];
                        smT[(d2 + 1) * 132 + r] = acc[mi][ni][p * 2 + 1];
                    }
                }
        }
        __syncthreads();
        if (wn < 2) {
            #pragma unroll
            for (int mi = 0; mi < 2; mi++)
                #pragma unroll
                for (int ni = 0; ni < 4; ni++) {
                    const int d = wn * 32 + ni * 8 + 2 * l4;
                    #pragma unroll
                    for (int p = 0; p < 2; p++) {
                        const int r = wm * 32 + mi * 16 + t4 + p * 8;
                        const int s = by * 128 + r;
                        const float x1a = acc[mi][ni][p * 2 + 0];
                        const float x1b = acc[mi][ni][p * 2 + 1];
                        const float x2a = smT[d * 132 + r];
                        const float x2b = smT[(d + 1) * 132 + r];
                        const float2 cl = *(const float2*)(cosb + (size_t)s * HD + d);
                        const float2 sl = *(const float2*)(sinb + (size_t)s * HD + d);
                        const float2 chh = *(const float2*)(cosb + (size_t)s * HD + d + 64);
                        const float2 shh = *(const float2*)(sinb + (size_t)s * HD + d + 64);
                        __half2 lo = __floats2half2_rn(x1a * cl.x - x2a * sl.x,
                                                       x1b * cl.y - x2b * sl.y);
                        __half2 hi = __floats2half2_rn(x2a * chh.x + x1a * shh.x,
                                                       x2b * chh.y + x1b * shh.y);
                        __half* o = outp + (size_t)s * nh * HD + h * HD + d;
                        *reinterpret_cast<__half2*>(o)      = lo;
                        *reinterpret_cast<__half2*>(o + 64) = hi;
                    }
                }
        }
    } else {
        #pragma unroll
        for (int pass = 0; pass < 2; pass++) {
            const bool writer = (pass == 0) ? (wn < 2) : (wn >= 2);
            if (writer) {
                #pragma unroll
                for (int mi = 0; mi < 2; mi++)
                    #pragma unroll
                    for (int ni = 0; ni < 4; ni++) {
                        const int dl = (wn - 2 * pass) * 32 + ni * 8 + 2 * l4;
                        #pragma unroll
                        for (int p = 0; p < 2; p++) {
                            const int r = wm * 32 + mi * 16 + t4 + p * 8;
                            smT[dl * 132 + r]       = acc[mi][ni][p * 2 + 0];
                            smT[(dl + 1) * 132 + r] = acc[mi][ni][p * 2 + 1];
                        }
                    }
            }
            __syncthreads();
            #pragma unroll 4
            for (int l = 0; l < 16; l++) {
                const int e  = l * 512 + tid;
                const int dl = e >> 7;
                const int sl = e & 127;
                vt[(size_t)h * HD * S_LEN + (size_t)(dl + pass * 64) * S_LEN
                   + by * 128 + sl] = __float2half_rn(smT[dl * 132 + sl]);
            }
            __syncthreads();
        }
    }
}

// ---------------------------------------------------------------------------
// Fused fp32 -> fp16 conversion of all 5 inputs in one launch.
// ---------------------------------------------------------------------------
#define CVT_B0 2097152
#define CVT_B1 6291456
#define CVT_B2 7340032
#define CVT_B3 8388608
#define CVT_B4 12582912
__global__ void cvt_all(const float4* __restrict__ hs, const float4* __restrict__ wq,
                        const float4* __restrict__ wk, const float4* __restrict__ wv,
                        const float4* __restrict__ wo,
                        __half2* __restrict__ hsh, __half2* __restrict__ wqh,
                        __half2* __restrict__ wkh, __half2* __restrict__ wvh,
                        __half2* __restrict__ woh)
{
    const int i = blockIdx.x * blockDim.x + threadIdx.x;
    if (i >= CVT_B4) return;
    const float4* src; __half2* dst; int j;
    if (i < CVT_B0)      { src = hs; dst = hsh; j = i; }
    else if (i < CVT_B1) { src = wq; dst = wqh; j = i - CVT_B0; }
    else if (i < CVT_B2) { src = wk; dst = wkh; j = i - CVT_B1; }
    else if (i < CVT_B3) { src = wv; dst = wvh; j = i - CVT_B2; }
    else                 { src = wo; dst = woh; j = i - CVT_B3; }
    float4 v = src[j];
    dst[j * 2 + 0] = __floats2half2_rn(v.x, v.y);
    dst[j * 2 + 1] = __floats2half2_rn(v.z, v.w);
}

// ---------------------------------------------------------------------------
// Causal softmax, 512 threads, one float4 per thread (2048 cols = 512 vecs).
// Heavy rows first (q descending). Writes W fp32 + Wh fp16 up to the
// 128-block containing q (upper blocks pre-zeroed by qkv's zero-fill CTAs).
// ---------------------------------------------------------------------------
__global__ __launch_bounds__(512) void softmax_causal(float* __restrict__ W,
                                                      __half* __restrict__ Wh)
{
    const int q = S_LEN - 1 - (int)blockIdx.x;   // heavy-first
    const int h = blockIdx.y;
    const long long off = ((long long)h * S_LEN + q) * S_LEN;
    float4* row4   = reinterpret_cast<float4*>(W + off);
    __half2* rowh2 = reinterpret_cast<__half2*>(Wh + off);
    const int L = q + 1;
    const int clip4 = (((q >> 7) + 1) << 7) >> 2;
    const int tid = threadIdx.x;
    __shared__ float red[16];

    const float NEGINF = -3.402823e38f;
    const int k0 = tid * 4;

    // --- load + masked max ---
    float4 va = make_float4(NEGINF, NEGINF, NEGINF, NEGINF);
    float mx = NEGINF;
    if (k0 < L) {
        va = row4[tid];
        mx = va.x;
        if (k0 + 1 < L) mx = fmaxf(mx, va.y);
        if (k0 + 2 < L) mx = fmaxf(mx, va.z);
        if (k0 + 3 < L) mx = fmaxf(mx, va.w);
    }
    #pragma unroll
    for (int o = 16; o; o >>= 1) mx = fmaxf(mx, __shfl_xor_sync(0xffffffffu, mx, o));
    if ((tid & 31) == 0) red[tid >> 5] = mx;
    __syncthreads();
    if (tid < 32) {
        float w2 = (tid < 16) ? red[tid] : NEGINF;
        #pragma unroll
        for (int o = 8; o; o >>= 1) w2 = fmaxf(w2, __shfl_xor_sync(0xffffffffu, w2, o));
        if (tid == 0) red[0] = w2;
    }
    __syncthreads();
    mx = red[0];
    __syncthreads();

    // --- exp + sum ---
    float s = 0.f;
    float4 e = make_float4(0.f, 0.f, 0.f, 0.f);
    if (k0 < L) {
        e.x = expf(va.x - mx);
        if (k0 + 1 < L) e.y = expf(va.y - mx);
        if (k0 + 2 < L) e.z = expf(va.z - mx);
        if (k0 + 3 < L) e.w = expf(va.w - mx);
        s = e.x + e.y + e.z + e.w;
    }
    #pragma unroll
    for (int o = 16; o; o >>= 1) s += __shfl_xor_sync(0xffffffffu, s, o);
    if ((tid & 31) == 0) red[tid >> 5] = s;
    __syncthreads();
    if (tid < 32) {
        float w2 = (tid < 16) ? red[tid] : 0.f;
        #pragma unroll
        for (int o = 8; o; o >>= 1) w2 += __shfl_xor_sync(0xffffffffu, w2, o);
        if (tid == 0) red[0] = w2;
    }
    __syncthreads();
    const float inv = 1.f / red[0];

    // --- write normalized W + Wh (clipped) ---
    if (tid < clip4) {
        float4 o4 = make_float4(e.x * inv, e.y * inv, e.z * inv, e.w * inv);
        row4[tid] = o4;
        rowh2[tid * 2 + 0] = __floats2half2_rn(o4.x, o4.y);
        rowh2[tid * 2 + 1] = __floats2half2_rn(o4.z, o4.w);
    }
}

// ---------------------------------------------------------------------------
extern "C" void kernel_launch(void* const* d_in, const int* in_sizes, int n_in,
                              void* d_out, int out_size)
{
    const float* hs   = (const float*)d_in[0];
    const float* wq   = (const float*)d_in[1];
    const float* wk   = (const float*)d_in[2];
    const float* wv   = (const float*)d_in[3];
    const float* wo   = (const float*)d_in[4];
    const float* cosb = (const float*)d_in[5];
    const float* sinb = (const float*)d_in[6];
    (void)in_sizes; (void)n_in;

    float* out = (float*)d_out;

    const long long OUT_ELEMS = (long long)S_LEN * NH * HD;
    const long long W_ELEMS   = (long long)NH * S_LEN * S_LEN;

    __half *hsh, *wqh, *wkh, *wvh, *woh, *qh, *kh, *vtp, *aoh, *whp;
    float  *wsc;
    cudaGetSymbolAddress((void**)&hsh, g_hsh);
    cudaGetSymbolAddress((void**)&wqh, g_wqh);
    cudaGetSymbolAddress((void**)&wkh, g_wkh);
    cudaGetSymbolAddress((void**)&wvh, g_wvh);
    cudaGetSymbolAddress((void**)&woh, g_woh);
    cudaGetSymbolAddress((void**)&qh,  g_qh);
    cudaGetSymbolAddress((void**)&kh,  g_kh);
    cudaGetSymbolAddress((void**)&vtp, g_vt);
    cudaGetSymbolAddress((void**)&aoh, g_aoh);
    cudaGetSymbolAddress((void**)&whp, g_wh);
    cudaGetSymbolAddress((void**)&wsc, g_w_scratch);

    float* W = ((long long)out_size >= OUT_ELEMS + W_ELEMS) ? (out + OUT_ELEMS) : wsc;

    static int attr_done = 0;
    if (!attr_done) {
        cudaFuncSetAttribute(mm_f16<128>, cudaFuncAttributeMaxDynamicSharedMemorySize, DYN_SMEM_128);
        cudaFuncSetAttribute(qkv_rope,    cudaFuncAttributeMaxDynamicSharedMemorySize, DYN_SMEM_128);
        attr_done = 1;
    }

    // 0) fp16 conversion of all inputs, one launch
    cvt_all<<<(CVT_B4 + 255) / 256, 256>>>(
        (const float4*)hs, (const float4*)wq, (const float4*)wk,
        (const float4*)wv, (const float4*)wo,
        (__half2*)hsh, (__half2*)wqh, (__half2*)wkh, (__half2*)wvh, (__half2*)woh);

    // 1) Merged QKV + RoPE + V-transpose + causal zero-fill (tail overlap)
    qkv_rope<<<dim3(48, 96), 512, DYN_SMEM_128>>>(hsh, wqh, wkh, wvh,
                                                  qh, kh, vtp, cosb, sinb, W);

    // 2) Scores: Q_h @ K_{h/4}^T * scaling -> fp32 W (heavy rows first)
    mm_f16<128><<<dim3(S_LEN / 128, S_LEN / 128, NH), 512, DYN_SMEM_128>>>(qh, kh, W,
        HD, NH * HD, NKV * HD, S_LEN,
        HD, HD, 2, (long long)S_LEN * S_LEN, SCALING, 1, 0);

    // 3) Softmax: W fp32 (clipped) + Wh fp16 (heavy rows first)
    softmax_causal<<<dim3(S_LEN, NH), 512>>>(W, whp);

    // 4) attn_out = W_h @ (V^T_{h/4})^T, K clipped -> fp16 (heavy rows first)
    mm_f16<128><<<dim3(1, S_LEN / 128, NH), 512, DYN_SMEM_128>>>(whp, vtp, aoh,
        S_LEN, S_LEN, S_LEN, NH * HD,
        (long long)S_LEN * S_LEN, (long long)HD * S_LEN, 2, HD, 1.f, 2, 1);

    // 5) out = attn_out @ wo^T -> fp32
    mm_f16<128><<<dim3(NH * HD / 128, S_LEN / 128), 512, DYN_SMEM_128>>>(aoh, woh, out,
        HDIM, HDIM, HDIM, NH * HD, 0, 0, 0, 0, 1.f, 0, 0);
}

// round 17
// speedup vs baseline: 1.0952x; 1.0952x over previous
#include <cuda_runtime.h>
#include <cuda_fp16.h>
#include <math.h>
#include <stdint.h>

// ---------------------------------------------------------------------------
// Problem constants: B=1, S=2048, H=4096, NH=32, NKV=8, HD=128
// ---------------------------------------------------------------------------
#define S_LEN 2048
#define HDIM  4096
#define NH    32
#define NKV   8
#define HD    128
#define SCALING 0.08838834764831843f  // 128^-0.5

// Device-global scratch (no runtime allocation allowed)
__device__ __half g_hsh[S_LEN * HDIM];
__device__ __half g_wqh[HDIM * HDIM];
__device__ __half g_wkh[NKV * HD * HDIM];
__device__ __half g_wvh[NKV * HD * HDIM];
__device__ __half g_woh[HDIM * HDIM];
__device__ __half g_qh [S_LEN * NH  * HD];   // fp16 Q post-rope
__device__ __half g_kh [S_LEN * NKV * HD];   // fp16 K post-rope
__device__ __half g_vt [NKV * HD * S_LEN];   // V^T per kv-head, fp16
__device__ __half g_aoh[S_LEN * NH  * HD];   // attn_out fp16
__device__ __half g_wh [(size_t)NH * S_LEN * S_LEN];      // fp16 weights operand
__device__ float  g_w_scratch[(size_t)NH * S_LEN * S_LEN]; // fallback fp32 W

// ---------------------------------------------------------------------------
// Helpers
// ---------------------------------------------------------------------------
__device__ __forceinline__ void mma_f16(float* c, const uint32_t* a,
                                        uint32_t b0, uint32_t b1) {
    asm volatile(
        "mma.sync.aligned.m16n8k16.row.col.f32.f16.f16.f32 "
        "{%0,%1,%2,%3}, {%4,%5,%6,%7}, {%8,%9}, {%0,%1,%2,%3};\n"
        : "+f"(c[0]), "+f"(c[1]), "+f"(c[2]), "+f"(c[3])
        : "r"(a[0]), "r"(a[1]), "r"(a[2]), "r"(a[3]), "r"(b0), "r"(b1));
}
__device__ __forceinline__ void ldsm4(uint32_t* r, uint32_t addr) {
    asm volatile("ldmatrix.sync.aligned.m8n8.x4.shared.b16 {%0,%1,%2,%3}, [%4];"
        : "=r"(r[0]), "=r"(r[1]), "=r"(r[2]), "=r"(r[3]) : "r"(addr));
}
__device__ __forceinline__ void cp16(uint32_t dst, const void* src) {
    asm volatile("cp.async.cg.shared.global [%0], [%1], 16;" :: "r"(dst), "l"(src));
}
#define CP_COMMIT() asm volatile("cp.async.commit_group;")
#define CP_WAIT1()  asm volatile("cp.async.wait_group 1;")
#define CP_WAIT0()  asm volatile("cp.async.wait_group 0;")

// Tile geometry: CTA 128x128, K-chunk 64 (128B fp16 rows, Swizzle<3,3,3>).
#define BM 128
#define BN 128
#define TILE_B 16384       // one 128x64 fp16 tile (128 rows x 128B)
#define STAGE_B 32768      // A tile + B tile
#define NSTAGE 3
#define DYN_SMEM (NSTAGE * STAGE_B)   // 98304

// ---------------------------------------------------------------------------
// General FP16 GEMM:  C[z] = alpha * A[z] @ B[z>>bShift]^T
// A[M,K] k-major fp16 (lda), B[N,K] k-major fp16 (ldb). C fp32 or fp16.
// 512 threads, 16 warps (4x4), warp tile 32x32.
// mode: 0 dense, 1 causal (skip bx>by; those CTAs zero-fill their C tile),
//       2 K clipped to (by+1)*128.
// Smem: 16B chunk c of row r at byte r*128 + ((c ^ (r&7))<<4).
// ---------------------------------------------------------------------------
__global__ __launch_bounds__(512) void mm_f16(
    const __half* __restrict__ A, const __half* __restrict__ B, void* __restrict__ Cv,
    int K, int lda, int ldb, int ldc,
    long long bsA, long long bsB, int bShift, long long bsC,
    float alpha, int mode, int outF16)
{
    const int bx = blockIdx.x, by = blockIdx.y, bz = blockIdx.z;
    const int tid  = threadIdx.x;

    if (mode == 1 && bx > by) {
        // Zero-fill this upper-triangle C tile (fp32) and exit.
        float* C = (float*)Cv + (long long)bz * bsC;
        const float4 z = make_float4(0.f, 0.f, 0.f, 0.f);
        #pragma unroll 4
        for (int i = tid; i < 128 * 32; i += 512) {
            const int r = i >> 5, c = (i & 31) << 2;
            *reinterpret_cast<float4*>(&C[(long long)(by * BM + r) * ldc + bx * BN + c]) = z;
        }
        return;
    }

    A += (long long)bz * bsA;
    B += (long long)(bz >> bShift) * bsB;

    const int Ktot = (mode == 2) ? min(K, (by + 1) * BM) : K;
    const int NT = Ktot >> 6;    // K-chunks of 64

    extern __shared__ __align__(128) char smem[];
    const uint32_t sb0 = (uint32_t)__cvta_generic_to_shared(smem);

    const int lane = tid & 31;
    const int w    = tid >> 5;
    const int wm   = w >> 2;
    const int wn   = w & 3;
    const int t4   = lane >> 2;
    const int l4   = lane & 3;

    // Loader: thread covers row rr, chunks cc and cc+4 of each tile.
    const int rr = tid >> 2;
    const int cc = tid & 3;
    const uint32_t offA0 = (uint32_t)(rr * 128 + (((cc    ) ^ (rr & 7)) << 4));
    const uint32_t offA1 = (uint32_t)(rr * 128 + (((cc + 4) ^ (rr & 7)) << 4));
    const __half* gA = A + (long long)(by * BM + rr) * lda + cc * 8;
    const __half* gB = B + (long long)(bx * BN + rr) * ldb + cc * 8;

    // ldmatrix per-lane byte offsets (within stage) for ksteps 0..3.
    uint32_t aoff[4], boff[4];
    {
        const int ra = wm * 32 + (lane & 15);
        const int rb = wn * 32 + (lane & 15);
        #pragma unroll
        for (int ks = 0; ks < 4; ks++) {
            const int cha = ks * 2 + (lane >> 4);
            aoff[ks] = (uint32_t)(ra * 128 + ((cha ^ (ra & 7)) << 4));
            boff[ks] = (uint32_t)(TILE_B + rb * 128 + ((cha ^ (rb & 7)) << 4));
        }
    }

    float acc[2][4][4];
    #pragma unroll
    for (int i = 0; i < 2; i++)
        #pragma unroll
        for (int j = 0; j < 4; j++)
            #pragma unroll
            for (int r = 0; r < 4; r++) acc[i][j][r] = 0.f;

    #pragma unroll
    for (int s = 0; s < 2; s++) {
        if (s < NT) {
            const uint32_t d = sb0 + s * STAGE_B;
            const __half* a0 = gA + s * 64;
            const __half* b0 = gB + s * 64;
            cp16(d + offA0,          a0);
            cp16(d + offA1,          a0 + 32);
            cp16(d + TILE_B + offA0, b0);
            cp16(d + TILE_B + offA1, b0 + 32);
        }
        CP_COMMIT();
    }

    for (int t = 0; t < NT; t++) {
        CP_WAIT1();
        __syncthreads();
        const uint32_t sb = sb0 + (t % NSTAGE) * STAGE_B;

        #pragma unroll
        for (int ks = 0; ks < 4; ks++) {
            uint32_t a[2][4], b[2][4];
            #pragma unroll
            for (int mi = 0; mi < 2; mi++) ldsm4(a[mi], sb + aoff[ks] + mi * 2048);
            #pragma unroll
            for (int p = 0; p < 2; p++)    ldsm4(b[p],  sb + boff[ks] + p * 2048);
            #pragma unroll
            for (int mi = 0; mi < 2; mi++)
                #pragma unroll
                for (int p = 0; p < 2; p++) {
                    mma_f16(acc[mi][p * 2 + 0], a[mi], b[p][0], b[p][2]);
                    mma_f16(acc[mi][p * 2 + 1], a[mi], b[p][1], b[p][3]);
                }
        }

        const int tn = t + 2;
        if (tn < NT) {
            const uint32_t d = sb0 + (tn % NSTAGE) * STAGE_B;
            const __half* a0 = gA + tn * 64;
            const __half* b0 = gB + tn * 64;
            cp16(d + offA0,          a0);
            cp16(d + offA1,          a0 + 32);
            cp16(d + TILE_B + offA0, b0);
            cp16(d + TILE_B + offA1, b0 + 32);
        }
        CP_COMMIT();
    }

    #pragma unroll
    for (int mi = 0; mi < 2; mi++) {
        const int r0 = by * BM + wm * 32 + mi * 16 + t4;
        #pragma unroll
        for (int ni = 0; ni < 4; ni++) {
            const int c0 = bx * BN + wn * 32 + ni * 8 + 2 * l4;
            float v0 = acc[mi][ni][0] * alpha, v1 = acc[mi][ni][1] * alpha;
            float v2 = acc[mi][ni][2] * alpha, v3 = acc[mi][ni][3] * alpha;
            if (outF16) {
                __half* C = (__half*)Cv + (long long)bz * bsC;
                *reinterpret_cast<__half2*>(&C[(long long)r0 * ldc + c0]) =
                    __floats2half2_rn(v0, v1);
                *reinterpret_cast<__half2*>(&C[(long long)(r0 + 8) * ldc + c0]) =
                    __floats2half2_rn(v2, v3);
            } else {
                float* C = (float*)Cv + (long long)bz * bsC;
                *reinterpret_cast<float2*>(&C[(long long)r0 * ldc + c0]) = make_float2(v0, v1);
                *reinterpret_cast<float2*>(&C[(long long)(r0 + 8) * ldc + c0]) = make_float2(v2, v3);
            }
        }
    }
}

// ---------------------------------------------------------------------------
// Merged QKV projection + RoPE + V-transpose (BK=64 mainloop).
// grid (48, 16): bx<32 -> Q head bx (rope), bx<40 -> K head bx-32 (rope),
// else V head bx-40 (transpose).
// ---------------------------------------------------------------------------
__global__ __launch_bounds__(512) void qkv_rope(
    const __half* __restrict__ hsA,
    const __half* __restrict__ wq, const __half* __restrict__ wk,
    const __half* __restrict__ wv,
    __half* __restrict__ qh, __half* __restrict__ kh, __half* __restrict__ vt,
    const float* __restrict__ cosb, const float* __restrict__ sinb)
{
    const int bx = blockIdx.x, by = blockIdx.y;

    const __half* Bw; int h; int epi;  // 0 rope-Q, 1 rope-K, 2 trans-V
    if (bx < 32)      { Bw = wq; h = bx;      epi = 0; }
    else if (bx < 40) { Bw = wk; h = bx - 32; epi = 1; }
    else              { Bw = wv; h = bx - 40; epi = 2; }

    extern __shared__ __align__(128) char smem[];
    const uint32_t sb0 = (uint32_t)__cvta_generic_to_shared(smem);
    float* smT = reinterpret_cast<float*>(smem);   // [64][132] overlay (post-drain)

    const int tid  = threadIdx.x;
    const int lane = tid & 31;
    const int w    = tid >> 5;
    const int wm   = w >> 2;
    const int wn   = w & 3;
    const int t4   = lane >> 2;
    const int l4   = lane & 3;

    const int rr = tid >> 2;
    const int cc = tid & 3;
    const uint32_t offA0 = (uint32_t)(rr * 128 + (((cc    ) ^ (rr & 7)) << 4));
    const uint32_t offA1 = (uint32_t)(rr * 128 + (((cc + 4) ^ (rr & 7)) << 4));
    const __half* gA = hsA + (long long)(by * BM + rr) * HDIM + cc * 8;
    const __half* gB = Bw  + (long long)(h  * BN + rr) * HDIM + cc * 8;

    uint32_t aoff[4], boff[4];
    {
        const int ra = wm * 32 + (lane & 15);
        const int rb = wn * 32 + (lane & 15);
        #pragma unroll
        for (int ks = 0; ks < 4; ks++) {
            const int cha = ks * 2 + (lane >> 4);
            aoff[ks] = (uint32_t)(ra * 128 + ((cha ^ (ra & 7)) << 4));
            boff[ks] = (uint32_t)(TILE_B + rb * 128 + ((cha ^ (rb & 7)) << 4));
        }
    }

    float acc[2][4][4];
    #pragma unroll
    for (int i = 0; i < 2; i++)
        #pragma unroll
        for (int j = 0; j < 4; j++)
            #pragma unroll
            for (int r = 0; r < 4; r++) acc[i][j][r] = 0.f;

    const int NT = HDIM >> 6;   // 64

    #pragma unroll
    for (int s = 0; s < 2; s++) {
        const uint32_t d = sb0 + s * STAGE_B;
        const __half* a0 = gA + s * 64;
        const __half* b0 = gB + s * 64;
        cp16(d + offA0,          a0);
        cp16(d + offA1,          a0 + 32);
        cp16(d + TILE_B + offA0, b0);
        cp16(d + TILE_B + offA1, b0 + 32);
        CP_COMMIT();
    }

    for (int t = 0; t < NT; t++) {
        CP_WAIT1();
        __syncthreads();
        const uint32_t sb = sb0 + (t % NSTAGE) * STAGE_B;

        #pragma unroll
        for (int ks = 0; ks < 4; ks++) {
            uint32_t a[2][4], b[2][4];
            #pragma unroll
            for (int mi = 0; mi < 2; mi++) ldsm4(a[mi], sb + aoff[ks] + mi * 2048);
            #pragma unroll
            for (int p = 0; p < 2; p++)    ldsm4(b[p],  sb + boff[ks] + p * 2048);
            #pragma unroll
            for (int mi = 0; mi < 2; mi++)
                #pragma unroll
                for (int p = 0; p < 2; p++) {
                    mma_f16(acc[mi][p * 2 + 0], a[mi], b[p][0], b[p][2]);
                    mma_f16(acc[mi][p * 2 + 1], a[mi], b[p][1], b[p][3]);
                }
        }

        const int tn = t + 2;
        if (tn < NT) {
            const uint32_t d = sb0 + (tn % NSTAGE) * STAGE_B;
            const __half* a0 = gA + tn * 64;
            const __half* b0 = gB + tn * 64;
            cp16(d + offA0,          a0);
            cp16(d + offA1,          a0 + 32);
            cp16(d + TILE_B + offA0, b0);
            cp16(d + TILE_B + offA1, b0 + 32);
        }
        CP_COMMIT();
    }

    // Drain async copies fully; stage buffer becomes the smT overlay.
    CP_WAIT0();
    __syncthreads();

    if (epi < 2) {
        // ---- RoPE epilogue ----
        const int nh = (epi == 0) ? NH : NKV;
        __half* outp = (epi == 0) ? qh : kh;
        if (wn >= 2) {
            #pragma unroll
            for (int mi = 0; mi < 2; mi++)
                #pragma unroll
                for (int ni = 0; ni < 4; ni++) {
                    const int d2 = (wn - 2) * 32 + ni * 8 + 2 * l4;
                    #pragma unroll
                    for (int p = 0; p < 2; p++) {
                        const int r = wm * 32 + mi * 16 + t4 + p * 8;
                        smT[d2 * 132 + r]       = acc[mi][ni][p * 2 + 0];
                        smT[(d2 + 1) * 132 + r] = acc[mi][ni][p * 2 + 1];
                    }
                }
        }
        __syncthreads();
        if (wn < 2) {
            #pragma unroll
            for (int mi = 0; mi < 2; mi++)
                #pragma unroll
                for (int ni = 0; ni < 4; ni++) {
                    const int d = wn * 32 + ni * 8 + 2 * l4;   // 0..63, even
                    #pragma unroll
                    for (int p = 0; p < 2; p++) {
                        const int r = wm * 32 + mi * 16 + t4 + p * 8;
                        const int s = by * 128 + r;
                        const float x1a = acc[mi][ni][p * 2 + 0];
                        const float x1b = acc[mi][ni][p * 2 + 1];
                        const float x2a = smT[d * 132 + r];
                        const float x2b = smT[(d + 1) * 132 + r];
                        const float2 cl = *(const float2*)(cosb + (size_t)s * HD + d);
                        const float2 sl = *(const float2*)(sinb + (size_t)s * HD + d);
                        const float2 chh = *(const float2*)(cosb + (size_t)s * HD + d + 64);
                        const float2 shh = *(const float2*)(sinb + (size_t)s * HD + d + 64);
                        __half2 lo = __floats2half2_rn(x1a * cl.x - x2a * sl.x,
                                                       x1b * cl.y - x2b * sl.y);
                        __half2 hi = __floats2half2_rn(x2a * chh.x + x1a * shh.x,
                                                       x2b * chh.y + x1b * shh.y);
                        __half* o = outp + (size_t)s * nh * HD + h * HD + d;
                        *reinterpret_cast<__half2*>(o)      = lo;
                        *reinterpret_cast<__half2*>(o + 64) = hi;
                    }
                }
        }
    } else {
        // ---- V transpose epilogue: vt[h][d][s] = proj[s][d] ----
        #pragma unroll
        for (int pass = 0; pass < 2; pass++) {
            const bool writer = (pass == 0) ? (wn < 2) : (wn >= 2);
            if (writer) {
                #pragma unroll
                for (int mi = 0; mi < 2; mi++)
                    #pragma unroll
                    for (int ni = 0; ni < 4; ni++) {
                        const int dl = (wn - 2 * pass) * 32 + ni * 8 + 2 * l4; // 0..63
                        #pragma unroll
                        for (int p = 0; p < 2; p++) {
                            const int r = wm * 32 + mi * 16 + t4 + p * 8;
                            smT[dl * 132 + r]       = acc[mi][ni][p * 2 + 0];
                            smT[(dl + 1) * 132 + r] = acc[mi][ni][p * 2 + 1];
                        }
                    }
            }
            __syncthreads();
            #pragma unroll 4
            for (int l = 0; l < 16; l++) {
                const int e  = l * 512 + tid;
                const int dl = e >> 7;
                const int sl = e & 127;
                vt[(size_t)h * HD * S_LEN + (size_t)(dl + pass * 64) * S_LEN
                   + by * 128 + sl] = __float2half_rn(smT[dl * 132 + sl]);
            }
            __syncthreads();
        }
    }
}

// ---------------------------------------------------------------------------
// Fused fp32 -> fp16 conversion of all 5 inputs in one launch.
// ---------------------------------------------------------------------------
#define CVT_B0 2097152    // hs   (2048*4096/4)
#define CVT_B1 6291456    // + wq (4096*4096/4)
#define CVT_B2 7340032    // + wk (1024*4096/4)
#define CVT_B3 8388608    // + wv
#define CVT_B4 12582912   // + wo
__global__ void cvt_all(const float4* __restrict__ hs, const float4* __restrict__ wq,
                        const float4* __restrict__ wk, const float4* __restrict__ wv,
                        const float4* __restrict__ wo,
                        __half2* __restrict__ hsh, __half2* __restrict__ wqh,
                        __half2* __restrict__ wkh, __half2* __restrict__ wvh,
                        __half2* __restrict__ woh)
{
    const int i = blockIdx.x * blockDim.x + threadIdx.x;
    if (i >= CVT_B4) return;
    const float4* src; __half2* dst; int j;
    if (i < CVT_B0)      { src = hs; dst = hsh; j = i; }
    else if (i < CVT_B1) { src = wq; dst = wqh; j = i - CVT_B0; }
    else if (i < CVT_B2) { src = wk; dst = wkh; j = i - CVT_B1; }
    else if (i < CVT_B3) { src = wv; dst = wvh; j = i - CVT_B2; }
    else                 { src = wo; dst = woh; j = i - CVT_B3; }
    float4 v = src[j];
    dst[j * 2 + 0] = __floats2half2_rn(v.x, v.y);
    dst[j * 2 + 1] = __floats2half2_rn(v.z, v.w);
}

// ---------------------------------------------------------------------------
// Causal softmax, float4 IO, 256 threads x 2 vectors (R9 shape).
// __expf (MUFU.EX2) replaces expf: ncu showed fma+alu ~58%/issue 62% —
// the polynomial was the issue bottleneck. Writes W fp32 + Wh fp16 up to the
// 128-block containing q (upper blocks pre-zeroed by the scores kernel).
// ---------------------------------------------------------------------------
__global__ __launch_bounds__(256) void softmax_causal(float* __restrict__ W,
                                                      __half* __restrict__ Wh)
{
    const int q = blockIdx.x;
    const int h = blockIdx.y;
    const long long off = ((long long)h * S_LEN + q) * S_LEN;
    float4* row4  = reinterpret_cast<float4*>(W + off);
    __half2* rowh2 = reinterpret_cast<__half2*>(Wh + off);
    const int L = q + 1;
    const int clip4 = (((q >> 7) + 1) << 7) >> 2;   // write bound in float4 units
    const int tid = threadIdx.x;
    __shared__ float red[32];

    float4 va[2];
    const float NEGINF = -3.402823e38f;

    float mx = NEGINF;
    #pragma unroll
    for (int j = 0; j < 2; j++) {
        const int iv = tid + j * 256;
        const int k0 = iv * 4;
        if (k0 < L) {
            float4 v = row4[iv];
            va[j] = v;
            mx = fmaxf(mx, v.x);
            if (k0 + 1 < L) mx = fmaxf(mx, v.y);
            if (k0 + 2 < L) mx = fmaxf(mx, v.z);
            if (k0 + 3 < L) mx = fmaxf(mx, v.w);
        }
    }
    #pragma unroll
    for (int o = 16; o; o >>= 1) mx = fmaxf(mx, __shfl_xor_sync(0xffffffffu, mx, o));
    if ((tid & 31) == 0) red[tid >> 5] = mx;
    __syncthreads();
    if (tid < 32) {
        float w2 = (tid < 8) ? red[tid] : NEGINF;
        #pragma unroll
        for (int o = 4; o; o >>= 1) w2 = fmaxf(w2, __shfl_xor_sync(0xffffffffu, w2, o));
        if (tid == 0) red[0] = w2;
    }
    __syncthreads();
    mx = red[0];
    __syncthreads();

    float s = 0.f;
    #pragma unroll
    for (int j = 0; j < 2; j++) {
        const int iv = tid + j * 256;
        const int k0 = iv * 4;
        float4 e = make_float4(0.f, 0.f, 0.f, 0.f);
        if (k0 < L) {
            e.x = __expf(va[j].x - mx);
            if (k0 + 1 < L) e.y = __expf(va[j].y - mx);
            if (k0 + 2 < L) e.z = __expf(va[j].z - mx);
            if (k0 + 3 < L) e.w = __expf(va[j].w - mx);
            s += e.x + e.y + e.z + e.w;
        }
        va[j] = e;
    }
    #pragma unroll
    for (int o = 16; o; o >>= 1) s += __shfl_xor_sync(0xffffffffu, s, o);
    if ((tid & 31) == 0) red[tid >> 5] = s;
    __syncthreads();
    if (tid < 32) {
        float w2 = (tid < 8) ? red[tid] : 0.f;
        #pragma unroll
        for (int o = 4; o; o >>= 1) w2 += __shfl_xor_sync(0xffffffffu, w2, o);
        if (tid == 0) red[0] = w2;
    }
    __syncthreads();
    const float inv = 1.f / red[0];

    #pragma unroll
    for (int j = 0; j < 2; j++) {
        const int iv = tid + j * 256;
        if (iv < clip4) {
            float4 o4 = make_float4(va[j].x * inv, va[j].y * inv,
                                    va[j].z * inv, va[j].w * inv);
            row4[iv] = o4;
            rowh2[iv * 2 + 0] = __floats2half2_rn(o4.x, o4.y);
            rowh2[iv * 2 + 1] = __floats2half2_rn(o4.z, o4.w);
        }
    }
}

// ---------------------------------------------------------------------------
extern "C" void kernel_launch(void* const* d_in, const int* in_sizes, int n_in,
                              void* d_out, int out_size)
{
    const float* hs   = (const float*)d_in[0];
    const float* wq   = (const float*)d_in[1];
    const float* wk   = (const float*)d_in[2];
    const float* wv   = (const float*)d_in[3];
    const float* wo   = (const float*)d_in[4];
    const float* cosb = (const float*)d_in[5];
    const float* sinb = (const float*)d_in[6];
    (void)in_sizes; (void)n_in;

    float* out = (float*)d_out;

    const long long OUT_ELEMS = (long long)S_LEN * NH * HD;
    const long long W_ELEMS   = (long long)NH * S_LEN * S_LEN;

    __half *hsh, *wqh, *wkh, *wvh, *woh, *qh, *kh, *vtp, *aoh, *whp;
    float  *wsc;
    cudaGetSymbolAddress((void**)&hsh, g_hsh);
    cudaGetSymbolAddress((void**)&wqh, g_wqh);
    cudaGetSymbolAddress((void**)&wkh, g_wkh);
    cudaGetSymbolAddress((void**)&wvh, g_wvh);
    cudaGetSymbolAddress((void**)&woh, g_woh);
    cudaGetSymbolAddress((void**)&qh,  g_qh);
    cudaGetSymbolAddress((void**)&kh,  g_kh);
    cudaGetSymbolAddress((void**)&vtp, g_vt);
    cudaGetSymbolAddress((void**)&aoh, g_aoh);
    cudaGetSymbolAddress((void**)&whp, g_wh);
    cudaGetSymbolAddress((void**)&wsc, g_w_scratch);

    float* W = ((long long)out_size >= OUT_ELEMS + W_ELEMS) ? (out + OUT_ELEMS) : wsc;

    static int attr_done = 0;
    if (!attr_done) {
        cudaFuncSetAttribute(mm_f16,   cudaFuncAttributeMaxDynamicSharedMemorySize, DYN_SMEM);
        cudaFuncSetAttribute(qkv_rope, cudaFuncAttributeMaxDynamicSharedMemorySize, DYN_SMEM);
        attr_done = 1;
    }

    // 0) fp16 conversion of all inputs, one launch
    cvt_all<<<(CVT_B4 + 255) / 256, 256>>>(
        (const float4*)hs, (const float4*)wq, (const float4*)wk,
        (const float4*)wv, (const float4*)wo,
        (__half2*)hsh, (__half2*)wqh, (__half2*)wkh, (__half2*)wvh, (__half2*)woh);

    // 1) Merged QKV projections + RoPE + V-transpose
    qkv_rope<<<dim3(48, S_LEN / BM), 512, DYN_SMEM>>>(hsh, wqh, wkh, wvh,
                                                      qh, kh, vtp, cosb, sinb);

    // 2) Scores: Q_h @ K_{h/4}^T * scaling -> fp32 W (skipped CTAs zero-fill)
    mm_f16<<<dim3(S_LEN / BN, S_LEN / BM, NH), 512, DYN_SMEM>>>(qh, kh, W,
        HD, NH * HD, NKV * HD, S_LEN,
        HD, HD, 2, (long long)S_LEN * S_LEN, SCALING, 1, 0);

    // 3) Softmax: W fp32 (clipped; upper blocks pre-zeroed) + Wh fp16
    softmax_causal<<<dim3(S_LEN, NH), 256>>>(W, whp);

    // 4) attn_out = W_h @ V_{h/4} (K clipped) -> fp16
    mm_f16<<<dim3(1, S_LEN / BM, NH), 512, DYN_SMEM>>>(whp, vtp, aoh,
        S_LEN, S_LEN, S_LEN, NH * HD,
        (long long)S_LEN * S_LEN, (long long)HD * S_LEN, 2, HD, 1.f, 2, 1);

    // 5) out = attn_out @ wo^T -> fp32
    mm_f16<<<dim3(NH * HD / BN, S_LEN / BM), 512, DYN_SMEM>>>(aoh, woh, out,
        HDIM, HDIM, HDIM, NH * HD, 0, 0, 0, 0, 1.f, 0, 0);
}